// round 7
// baseline (speedup 1.0000x reference)
#include <cuda_runtime.h>

#define Bsz 64
#define Ssz 128
#define Fdim 16
#define Hdim 64
#define XPAD 132
#define SCALE 0.17677669529663688f
#define GP 10

typedef unsigned long long u64;

__device__ __forceinline__ u64 pk(float a, float b) {
    u64 r; asm("mov.b64 %0, {%1,%2};" : "=l"(r) : "f"(a), "f"(b)); return r;
}
__device__ __forceinline__ u64 fma2(u64 a, u64 b, u64 c) {
    u64 d; asm("fma.rn.f32x2 %0, %1, %2, %3;" : "=l"(d) : "l"(a), "l"(b), "l"(c)); return d;
}
__device__ __forceinline__ float2 upk(u64 v) {
    float2 r; asm("mov.b64 {%0,%1}, %2;" : "=f"(r.x), "=f"(r.y) : "l"(v)); return r;
}
__device__ __forceinline__ float sigm(float x) { return __fdividef(1.f, 1.f + __expf(-x)); }
__device__ __forceinline__ float tanh_(float x) { return 1.f - __fdividef(2.f, __expf(2.f * x) + 1.f); }

// scratch
__device__ float g_lstm[2u * Bsz * Fdim * Ssz * Hdim];   // [br][b][f][s][h]
__device__ float g_qk[2048u * 128 * 128];                // [pq][row][s]  rows 0-63 q(scaled), 64-127 k
__device__ float g_pooled[2u * Bsz * Fdim * Hdim];
__device__ ulonglong2 g_w2p[32 * 128 * 32];              // dup-packed qk weights [pair][row][j2]
__device__ float g_WvT[32 * 64 * 64];                    // [pair][j][h]
__device__ float g_WoT[32 * 64 * 64];                    // [pair][h][o]

// ---------------------------------------------------------------------------
// Prep: pre-transform attention weights.
// ---------------------------------------------------------------------------
__global__ void prep_kernel(const float* __restrict__ wd_aw, const float* __restrict__ rd_aw,
                            const float* __restrict__ wd_ow, const float* __restrict__ rd_ow)
{
    int f = blockIdx.x, br = blockIdx.y, tid = threadIdx.x;
    const float* aw = (br ? rd_aw : wd_aw) + (size_t)f * 192 * 64;
    const float* ow = (br ? rd_ow : wd_ow) + (size_t)f * 64 * 64;
    int pair = br * Fdim + f;
    for (int i = tid; i < 128 * 32; i += 256) {
        int row = i >> 5, j2 = i & 31;
        float sc = (row < 64) ? SCALE : 1.f;
        float w0 = aw[row * 64 + 2 * j2] * sc;
        float w1 = aw[row * 64 + 2 * j2 + 1] * sc;
        g_w2p[((size_t)pair * 128 + row) * 32 + j2] = make_ulonglong2(pk(w0, w0), pk(w1, w1));
    }
    for (int i = tid; i < 4096; i += 256) {
        int j = i >> 6, h = i & 63;
        g_WvT[(size_t)pair * 4096 + j * 64 + h] = aw[(128 + h) * 64 + j];
    }
    for (int i = tid; i < 4096; i += 256) {
        int h = i >> 6, o = i & 63;
        g_WoT[(size_t)pair * 4096 + h * 64 + o] = ow[o * 64 + h];
    }
}

// ---------------------------------------------------------------------------
// LSTM: R3 body + gates_s padded to GP=10 (bank-conflict fix).
// ---------------------------------------------------------------------------
__global__ __launch_bounds__(256, 2) void lstm_kernel(
    const float* __restrict__ wd_x, const float* __restrict__ rd_x,
    const float* __restrict__ wd_Wih, const float* __restrict__ wd_Whh,
    const float* __restrict__ wd_bih, const float* __restrict__ wd_bhh,
    const float* __restrict__ rd_Wih, const float* __restrict__ rd_Whh,
    const float* __restrict__ rd_bih, const float* __restrict__ rd_bhh)
{
    int bc = blockIdx.x, f = blockIdx.y, br = blockIdx.z;
    int bBase = bc * 8;
    const float* x   = br ? rd_x   : wd_x;
    const float* Wih = br ? rd_Wih : wd_Wih;
    const float* Whh = br ? rd_Whh : wd_Whh;
    const float* bih = br ? rd_bih : wd_bih;
    const float* bhh = br ? rd_bhh : wd_bhh;

    __shared__ __align__(16) float h_s[64 * 8];
    __shared__ __align__(16) float c_s[64 * 8];
    __shared__ __align__(16) float gates_s[256 * GP];
    __shared__ __align__(16) float x_s[128 * 8];

    int tid = threadIdx.x;
    for (int i = tid; i < 128 * 8; i += 256) {
        int t = i >> 3, b = i & 7;
        x_s[i] = x[(size_t)(bBase + b) * Ssz * Fdim + t * Fdim + f];
    }
    for (int i = tid; i < 64 * 8; i += 256) { h_s[i] = 0.f; c_s[i] = 0.f; }

    int g = tid;
    float wih  = Wih[f * 256 + g];
    float bias = bih[f * 256 + g] + bhh[f * 256 + g];
    u64 wih2 = pk(wih, wih), bias2 = pk(bias, bias);

    float w[64];
#pragma unroll
    for (int j = 0; j < 64; j += 4) {
        float4 v = *(const float4*)&Whh[((size_t)f * 256 + g) * 64 + j];
        w[j] = v.x; w[j + 1] = v.y; w[j + 2] = v.z; w[j + 3] = v.w;
    }
    __syncthreads();

    for (int t = 0; t < Ssz; t++) {
        u64 acc0, acc1, acc2, acc3;
        {
            const u64* xp = (const u64*)&x_s[t * 8];
            acc0 = fma2(wih2, xp[0], bias2);
            acc1 = fma2(wih2, xp[1], bias2);
            acc2 = fma2(wih2, xp[2], bias2);
            acc3 = fma2(wih2, xp[3], bias2);
        }
#pragma unroll
        for (int j = 0; j < 64; j++) {
            u64 w2 = pk(w[j], w[j]);
            const ulonglong2* hp = (const ulonglong2*)&h_s[j * 8];
            ulonglong2 hA = hp[0], hB = hp[1];
            acc0 = fma2(w2, hA.x, acc0); acc1 = fma2(w2, hA.y, acc1);
            acc2 = fma2(w2, hB.x, acc2); acc3 = fma2(w2, hB.y, acc3);
        }
        {
            u64* gp = (u64*)&gates_s[g * GP];
            gp[0] = acc0; gp[1] = acc1; gp[2] = acc2; gp[3] = acc3;
        }
        __syncthreads();
        {
            int k = tid & 63, bg = tid >> 6;
            float2 iv = *(const float2*)&gates_s[k * GP + bg * 2];
            float2 fv = *(const float2*)&gates_s[(64 + k) * GP + bg * 2];
            float2 gv = *(const float2*)&gates_s[(128 + k) * GP + bg * 2];
            float2 ov = *(const float2*)&gates_s[(192 + k) * GP + bg * 2];
            float2 cv = *(const float2*)&c_s[k * 8 + bg * 2];
            float2 cn, hn;
            cn.x = sigm(fv.x) * cv.x + sigm(iv.x) * tanh_(gv.x); hn.x = sigm(ov.x) * tanh_(cn.x);
            cn.y = sigm(fv.y) * cv.y + sigm(iv.y) * tanh_(gv.y); hn.y = sigm(ov.y) * tanh_(cn.y);
            *(float2*)&c_s[k * 8 + bg * 2] = cn;
            *(float2*)&h_s[k * 8 + bg * 2] = hn;
            size_t gb = ((((size_t)br * Bsz + bBase + bg * 2) * Fdim + f) * Ssz + t) * Hdim + k;
            const size_t bs = (size_t)Fdim * Ssz * Hdim;
            g_lstm[gb] = hn.x; g_lstm[gb + bs] = hn.y;
        }
        __syncthreads();
    }
}

// ---------------------------------------------------------------------------
// Proj kernel: xT in smem (34 KB), 4-row register-blocked, writes g_qk.
// ---------------------------------------------------------------------------
#define PROJ_SMEM_FLOATS (64 * XPAD)

__global__ __launch_bounds__(256, 3) void proj_kernel(
    const float* __restrict__ wd_ab, const float* __restrict__ rd_ab)
{
    int f = blockIdx.x, b = blockIdx.y, br = blockIdx.z;
    const float* ab = br ? rd_ab : wd_ab;

    extern __shared__ __align__(16) float smp[];
    float* xT = smp;   // [64][XPAD]

    int tid = threadIdx.x, lane = tid & 31, warp = tid >> 5;
    int pairW = br * Fdim + f;
    size_t pq = ((size_t)(br * Bsz + b) * Fdim + f);

    const float* xsrc = g_lstm + pq * Ssz * Hdim;
    for (int i = tid * 4; i < Ssz * Hdim; i += 1024) {
        int s = i >> 6, h = i & 63;
        float4 v = *(const float4*)&xsrc[i];
        xT[(h + 0) * XPAD + s] = v.x; xT[(h + 1) * XPAD + s] = v.y;
        xT[(h + 2) * XPAD + s] = v.z; xT[(h + 3) * XPAD + s] = v.w;
    }
    __syncthreads();

    float* qout = g_qk + pq * 16384;
#pragma unroll 1
    for (int rg = 0; rg < 4; rg++) {
        int row0 = warp * 16 + rg * 4;
        float scl = (row0 < 64) ? SCALE : 1.f;
        u64 a00, a01, a10, a11, a20, a21, a30, a31;
        {
            float b0 = ab[f * 192 + row0 + 0] * scl;
            float b1 = ab[f * 192 + row0 + 1] * scl;
            float b2 = ab[f * 192 + row0 + 2] * scl;
            float b3 = ab[f * 192 + row0 + 3] * scl;
            a00 = pk(b0, b0); a01 = a00;
            a10 = pk(b1, b1); a11 = a10;
            a20 = pk(b2, b2); a21 = a20;
            a30 = pk(b3, b3); a31 = a30;
        }
        const ulonglong2* wbase = &g_w2p[((size_t)pairW * 128 + row0) * 32];
#pragma unroll
        for (int j2 = 0; j2 < 32; j2++) {
            ulonglong2 x0 = *(const ulonglong2*)&xT[(2 * j2) * XPAD + lane * 4];
            ulonglong2 x1 = *(const ulonglong2*)&xT[(2 * j2 + 1) * XPAD + lane * 4];
            ulonglong2 w0 = __ldg(&wbase[0 * 32 + j2]);
            ulonglong2 w1 = __ldg(&wbase[1 * 32 + j2]);
            ulonglong2 w2 = __ldg(&wbase[2 * 32 + j2]);
            ulonglong2 w3 = __ldg(&wbase[3 * 32 + j2]);
            a00 = fma2(w0.x, x0.x, a00); a01 = fma2(w0.x, x0.y, a01);
            a00 = fma2(w0.y, x1.x, a00); a01 = fma2(w0.y, x1.y, a01);
            a10 = fma2(w1.x, x0.x, a10); a11 = fma2(w1.x, x0.y, a11);
            a10 = fma2(w1.y, x1.x, a10); a11 = fma2(w1.y, x1.y, a11);
            a20 = fma2(w2.x, x0.x, a20); a21 = fma2(w2.x, x0.y, a21);
            a20 = fma2(w2.y, x1.x, a20); a21 = fma2(w2.y, x1.y, a21);
            a30 = fma2(w3.x, x0.x, a30); a31 = fma2(w3.x, x0.y, a31);
            a30 = fma2(w3.y, x1.x, a30); a31 = fma2(w3.y, x1.y, a31);
        }
        *(ulonglong2*)&qout[(row0 + 0) * 128 + lane * 4] = make_ulonglong2(a00, a01);
        *(ulonglong2*)&qout[(row0 + 1) * 128 + lane * 4] = make_ulonglong2(a10, a11);
        *(ulonglong2*)&qout[(row0 + 2) * 128 + lane * 4] = make_ulonglong2(a20, a21);
        *(ulonglong2*)&qout[(row0 + 3) * 128 + lane * 4] = make_ulonglong2(a30, a31);
    }
}

// ---------------------------------------------------------------------------
// Scores kernel: kT in smem (34 KB), q via __ldg broadcast, softmax with
// recompute-exp (keeps regs <= 85 for 3 blocks/SM), epilogue included.
// ---------------------------------------------------------------------------
#define SCORES_SMEM_FLOATS (64 * XPAD + 2048 + 256 + 128 + 64)

__global__ __launch_bounds__(256, 3) void scores_kernel(
    const float* __restrict__ wd_ab, const float* __restrict__ wd_ob,
    const float* __restrict__ rd_ab, const float* __restrict__ rd_ob,
    float* __restrict__ d_out)
{
    int f = blockIdx.x, b = blockIdx.y, br = blockIdx.z;
    const float* ab = br ? rd_ab : wd_ab;
    const float* ob = br ? rd_ob : wd_ob;

    extern __shared__ __align__(16) float sms[];
    float* kT        = sms;                 // [64][XPAD]
    float* wbar_part = sms + 64 * XPAD;     // [8][2][128]
    float* wbar_s    = wbar_part + 2048;    // [2][128]
    float* xw        = wbar_s + 256;        // [2][64]
    float* o_mean    = xw + 128;            // [64]

    int tid = threadIdx.x, lane = tid & 31, warp = tid >> 5;
    int pairW = br * Fdim + f;
    size_t pq = ((size_t)(br * Bsz + b) * Fdim + f);
    const float* qk = g_qk + pq * 16384;

    // load kT (rows 64-127) coalesced into smem
    for (int i = tid * 4; i < 64 * 128; i += 1024) {
        int row = i >> 7, s = i & 127;
        float4 v = *(const float4*)&qk[(64 + row) * 128 + s];
        *(float4*)&kT[row * XPAD + s] = v;
    }
    __syncthreads();

    float wbar_reg[8] = {0, 0, 0, 0, 0, 0, 0, 0};
    float* wout_base = d_out + 128 + (size_t)br * ((size_t)Fdim * Bsz * Ssz * Ssz)
                     + (((size_t)f * Bsz + b) * Ssz) * Ssz;

#pragma unroll 1
    for (int m = 0; m < 4; m++) {
        int qi0 = (warp << 4) + (m << 2);
        u64 acc[2][8];
        float sums[8];
#pragma unroll
        for (int n = 0; n < 2; n++) {
#pragma unroll
            for (int i = 0; i < 8; i++) acc[n][i] = 0ull;
#pragma unroll
            for (int d = 0; d < 32; d++) {
                int hg = (n << 5) + d;
                float4 qf = __ldg((const float4*)&qk[hg * 128 + qi0]);
                ulonglong2 kv = *(const ulonglong2*)&kT[hg * XPAD + lane * 4];
                u64 q0 = pk(qf.x, qf.x), q1 = pk(qf.y, qf.y);
                u64 q2 = pk(qf.z, qf.z), q3 = pk(qf.w, qf.w);
                acc[n][0] = fma2(q0, kv.x, acc[n][0]); acc[n][1] = fma2(q0, kv.y, acc[n][1]);
                acc[n][2] = fma2(q1, kv.x, acc[n][2]); acc[n][3] = fma2(q1, kv.y, acc[n][3]);
                acc[n][4] = fma2(q2, kv.x, acc[n][4]); acc[n][5] = fma2(q2, kv.y, acc[n][5]);
                acc[n][6] = fma2(q3, kv.x, acc[n][6]); acc[n][7] = fma2(q3, kv.y, acc[n][7]);
            }
#pragma unroll
            for (int v = 0; v < 4; v++) {
                float2 p0 = upk(acc[n][2 * v]), p1 = upk(acc[n][2 * v + 1]);
                sums[n * 4 + v] = (__expf(p0.x) + __expf(p0.y)) + (__expf(p1.x) + __expf(p1.y));
            }
        }
#pragma unroll
        for (int off = 16; off > 0; off >>= 1) {
            float t0 = __shfl_xor_sync(0xffffffffu, sums[0], off);
            float t1 = __shfl_xor_sync(0xffffffffu, sums[1], off);
            float t2 = __shfl_xor_sync(0xffffffffu, sums[2], off);
            float t3 = __shfl_xor_sync(0xffffffffu, sums[3], off);
            float t4 = __shfl_xor_sync(0xffffffffu, sums[4], off);
            float t5 = __shfl_xor_sync(0xffffffffu, sums[5], off);
            float t6 = __shfl_xor_sync(0xffffffffu, sums[6], off);
            float t7 = __shfl_xor_sync(0xffffffffu, sums[7], off);
            sums[0] += t0; sums[1] += t1; sums[2] += t2; sums[3] += t3;
            sums[4] += t4; sums[5] += t5; sums[6] += t6; sums[7] += t7;
        }
#pragma unroll
        for (int v = 0; v < 4; v++) {
            float2 p00 = upk(acc[0][2 * v]), p01 = upk(acc[0][2 * v + 1]);
            float2 p10 = upk(acc[1][2 * v]), p11 = upk(acc[1][2 * v + 1]);
            float i0 = __fdividef(1.f, sums[v]);
            float i1 = __fdividef(1.f, sums[4 + v]);
            float e00 = __expf(p00.x) * i0, e01 = __expf(p00.y) * i0;
            float e02 = __expf(p01.x) * i0, e03 = __expf(p01.y) * i0;
            float e10 = __expf(p10.x) * i1, e11 = __expf(p10.y) * i1;
            float e12 = __expf(p11.x) * i1, e13 = __expf(p11.y) * i1;
            wbar_reg[0] += e00; wbar_reg[1] += e01; wbar_reg[2] += e02; wbar_reg[3] += e03;
            wbar_reg[4] += e10; wbar_reg[5] += e11; wbar_reg[6] += e12; wbar_reg[7] += e13;
            float4 o4;
            o4.x = 0.5f * (e00 + e10); o4.y = 0.5f * (e01 + e11);
            o4.z = 0.5f * (e02 + e12); o4.w = 0.5f * (e03 + e13);
            *(float4*)&wout_base[(size_t)(qi0 + v) * Ssz + lane * 4] = o4;
        }
    }
    *(float4*)&wbar_part[(warp * 2 + 0) * 128 + lane * 4] =
        make_float4(wbar_reg[0], wbar_reg[1], wbar_reg[2], wbar_reg[3]);
    *(float4*)&wbar_part[(warp * 2 + 1) * 128 + lane * 4] =
        make_float4(wbar_reg[4], wbar_reg[5], wbar_reg[6], wbar_reg[7]);
    __syncthreads();

    // ---- epilogue ----
    {
        int n = tid >> 7, k = tid & 127;
        float a = 0.f;
#pragma unroll
        for (int wpi = 0; wpi < 8; wpi++) a += wbar_part[(wpi * 2 + n) * 128 + k];
        wbar_s[n * 128 + k] = a * (1.f / 128.f);
    }
    __syncthreads();
    if (tid < 128) {   // xw[n][j] = sum_k wbar_s[n][k] * x[k][j]  (x from global)
        int n = tid >> 6, j = tid & 63;
        const float* xg = g_lstm + pq * Ssz * Hdim + j;
        float a = 0.f;
#pragma unroll 4
        for (int k = 0; k < 128; k++)
            a += wbar_s[n * 128 + k] * __ldg(&xg[k * 64]);
        xw[tid] = a;
    }
    __syncthreads();
    if (tid < 64) {
        int h = tid, n = h >> 5;
        float a = ab[f * 192 + 128 + h];
        const float* wvp = g_WvT + (size_t)pairW * 4096;
        for (int j = 0; j < 64; j++) a += wvp[j * 64 + h] * xw[n * 64 + j];
        o_mean[h] = a;
    }
    __syncthreads();
    if (tid < 64) {
        int o = tid;
        float a = ob[f * 64 + o];
        const float* wop = g_WoT + (size_t)pairW * 4096;
        for (int h = 0; h < 64; h++) a += wop[h * 64 + o] * o_mean[h];
        g_pooled[(((size_t)br * Bsz + b) * Fdim + f) * 64 + o] = a;
    }
}

// ---------------------------------------------------------------------------
// Final: fused both outputs, 256 threads.
// ---------------------------------------------------------------------------
__global__ __launch_bounds__(256) void final_kernel(
    const float* __restrict__ statin, const float* __restrict__ tg,
    const float* __restrict__ d1w, const float* __restrict__ d1b,
    const float* __restrict__ d2w, const float* __restrict__ d2b,
    const float* __restrict__ t1w, const float* __restrict__ t1b,
    const float* __restrict__ t2w, const float* __restrict__ t2b,
    const float* __restrict__ fcw, const float* __restrict__ fcb,
    float* __restrict__ out)
{
    __shared__ float s1[64], sf[32], t1v[16], tf[8], r0s[8], r1s[8];
    int b = blockIdx.x, tid = threadIdx.x;
    int lane = tid & 31, warp = tid >> 5;
    if (tid < 64) {
        float a = d1b[tid];
        for (int i = 0; i < 32; i++) a += statin[b * 32 + i] * d1w[tid * 32 + i];
        s1[tid] = fmaxf(a, 0.f);
    }
    if (tid < 16) t1v[tid] = fmaxf(t1b[tid] + tg[b] * t1w[tid], 0.f);
    __syncthreads();
    if (tid < 32) {
        float a = d2b[tid];
        for (int i = 0; i < 64; i++) a += s1[i] * d2w[tid * 64 + i];
        sf[tid] = fmaxf(a, 0.f);
    }
    if (tid < 8) {
        float a = t2b[tid];
        for (int i = 0; i < 16; i++) a += t1v[i] * t2w[tid * 16 + i];
        tf[tid] = fmaxf(a, 0.f);
    }
    __syncthreads();
    float a0 = 0.f, a1 = 0.f;
    for (int i = tid; i < 2088; i += 256) {
        float cv;
        if (i < 1024)      cv = g_pooled[(size_t)b * 1024 + i];
        else if (i < 2048) cv = g_pooled[(size_t)(Bsz + b) * 1024 + (i - 1024)];
        else if (i < 2080) cv = sf[i - 2048];
        else               cv = tf[i - 2080];
        a0 = fmaf(cv, fcw[i], a0);
        a1 = fmaf(cv, fcw[2088 + i], a1);
    }
#pragma unroll
    for (int off = 16; off > 0; off >>= 1) {
        float u0 = __shfl_xor_sync(0xffffffffu, a0, off);
        float u1 = __shfl_xor_sync(0xffffffffu, a1, off);
        a0 += u0; a1 += u1;
    }
    if (lane == 0) { r0s[warp] = a0; r1s[warp] = a1; }
    __syncthreads();
    if (tid == 0) {
        float s0v = fcb[0], s1v = fcb[1];
#pragma unroll
        for (int wpi = 0; wpi < 8; wpi++) { s0v += r0s[wpi]; s1v += r1s[wpi]; }
        out[b * 2 + 0] = s0v;
        out[b * 2 + 1] = s1v;
    }
}

extern "C" void kernel_launch(void* const* d_in, const int* in_sizes, int n_in,
                              void* d_out, int out_size)
{
    const float* wd_x    = (const float*)d_in[0];
    const float* rd_x    = (const float*)d_in[1];
    const float* statin  = (const float*)d_in[2];
    const float* tg      = (const float*)d_in[3];
    const float* wd_Wih  = (const float*)d_in[4];
    const float* wd_Whh  = (const float*)d_in[5];
    const float* wd_bih  = (const float*)d_in[6];
    const float* wd_bhh  = (const float*)d_in[7];
    const float* rd_Wih  = (const float*)d_in[8];
    const float* rd_Whh  = (const float*)d_in[9];
    const float* rd_bih  = (const float*)d_in[10];
    const float* rd_bhh  = (const float*)d_in[11];
    const float* wd_aw   = (const float*)d_in[12];
    const float* wd_ab   = (const float*)d_in[13];
    const float* wd_ow   = (const float*)d_in[14];
    const float* wd_ob   = (const float*)d_in[15];
    const float* rd_aw   = (const float*)d_in[16];
    const float* rd_ab   = (const float*)d_in[17];
    const float* rd_ow   = (const float*)d_in[18];
    const float* rd_ob   = (const float*)d_in[19];
    const float* d1w     = (const float*)d_in[20];
    const float* d1b     = (const float*)d_in[21];
    const float* d2w     = (const float*)d_in[22];
    const float* d2b     = (const float*)d_in[23];
    const float* t1w     = (const float*)d_in[24];
    const float* t1b     = (const float*)d_in[25];
    const float* t2w     = (const float*)d_in[26];
    const float* t2b     = (const float*)d_in[27];
    const float* fcw     = (const float*)d_in[28];
    const float* fcb     = (const float*)d_in[29];
    float* out = (float*)d_out;

    cudaFuncSetAttribute(proj_kernel, cudaFuncAttributeMaxDynamicSharedMemorySize,
                         PROJ_SMEM_FLOATS * 4);
    cudaFuncSetAttribute(scores_kernel, cudaFuncAttributeMaxDynamicSharedMemorySize,
                         SCORES_SMEM_FLOATS * 4);

    prep_kernel<<<dim3(Fdim, 2), 256>>>(wd_aw, rd_aw, wd_ow, rd_ow);

    lstm_kernel<<<dim3(8, Fdim, 2), 256>>>(
        wd_x, rd_x, wd_Wih, wd_Whh, wd_bih, wd_bhh, rd_Wih, rd_Whh, rd_bih, rd_bhh);

    proj_kernel<<<dim3(Fdim, Bsz, 2), 256, PROJ_SMEM_FLOATS * 4>>>(wd_ab, rd_ab);

    scores_kernel<<<dim3(Fdim, Bsz, 2), 256, SCORES_SMEM_FLOATS * 4>>>(
        wd_ab, wd_ob, rd_ab, rd_ob, out);

    final_kernel<<<Bsz, 256>>>(
        statin, tg, d1w, d1b, d2w, d2b, t1w, t1b, t2w, t2b, fcw, fcb, out);
}

// round 8
// speedup vs baseline: 1.0143x; 1.0143x over previous
#include <cuda_runtime.h>

#define Bsz 64
#define Ssz 128
#define Fdim 16
#define Hdim 64
#define XPAD 132
#define SCALE 0.17677669529663688f
#define GP 10

typedef unsigned long long u64;

__device__ __forceinline__ u64 pk(float a, float b) {
    u64 r; asm("mov.b64 %0, {%1,%2};" : "=l"(r) : "f"(a), "f"(b)); return r;
}
__device__ __forceinline__ u64 fma2(u64 a, u64 b, u64 c) {
    u64 d; asm("fma.rn.f32x2 %0, %1, %2, %3;" : "=l"(d) : "l"(a), "l"(b), "l"(c)); return d;
}
__device__ __forceinline__ float2 upk(u64 v) {
    float2 r; asm("mov.b64 {%0,%1}, %2;" : "=f"(r.x), "=f"(r.y) : "l"(v)); return r;
}
__device__ __forceinline__ float tanhap(float x) {
    float y; asm("tanh.approx.f32 %0, %1;" : "=f"(y) : "f"(x)); return y;
}
__device__ __forceinline__ float sigm_ap(float x) {
    return fmaf(0.5f, tanhap(0.5f * x), 0.5f);
}

// scratch
__device__ float g_lstm[2u * Bsz * Fdim * Ssz * Hdim];   // [br][b][f][s][h]
__device__ float g_qk[2048u * 128 * 128];                // [pq][row][s]  rows 0-63 q(scaled), 64-127 k
__device__ float g_pooled[2u * Bsz * Fdim * Hdim];
__device__ ulonglong2 g_w2p[32 * 128 * 32];              // dup-packed qk weights [pair][row][j2]
__device__ float g_WvT[32 * 64 * 64];                    // [pair][j][h]
__device__ float g_WoT[32 * 64 * 64];                    // [pair][h][o]

// ---------------------------------------------------------------------------
// Prep: pre-transform attention weights.
// ---------------------------------------------------------------------------
__global__ void prep_kernel(const float* __restrict__ wd_aw, const float* __restrict__ rd_aw,
                            const float* __restrict__ wd_ow, const float* __restrict__ rd_ow)
{
    int f = blockIdx.x, br = blockIdx.y, tid = threadIdx.x;
    const float* aw = (br ? rd_aw : wd_aw) + (size_t)f * 192 * 64;
    const float* ow = (br ? rd_ow : wd_ow) + (size_t)f * 64 * 64;
    int pair = br * Fdim + f;
    for (int i = tid; i < 128 * 32; i += 256) {
        int row = i >> 5, j2 = i & 31;
        float sc = (row < 64) ? SCALE : 1.f;
        float w0 = aw[row * 64 + 2 * j2] * sc;
        float w1 = aw[row * 64 + 2 * j2 + 1] * sc;
        g_w2p[((size_t)pair * 128 + row) * 32 + j2] = make_ulonglong2(pk(w0, w0), pk(w1, w1));
    }
    for (int i = tid; i < 4096; i += 256) {
        int j = i >> 6, h = i & 63;
        g_WvT[(size_t)pair * 4096 + j * 64 + h] = aw[(128 + h) * 64 + j];
    }
    for (int i = tid; i < 4096; i += 256) {
        int h = i >> 6, o = i & 63;
        g_WoT[(size_t)pair * 4096 + h * 64 + o] = ow[o * 64 + h];
    }
}

// ---------------------------------------------------------------------------
// LSTM: R3 body, GP-padded gates, tanh.approx activations.
// ---------------------------------------------------------------------------
__global__ __launch_bounds__(256, 2) void lstm_kernel(
    const float* __restrict__ wd_x, const float* __restrict__ rd_x,
    const float* __restrict__ wd_Wih, const float* __restrict__ wd_Whh,
    const float* __restrict__ wd_bih, const float* __restrict__ wd_bhh,
    const float* __restrict__ rd_Wih, const float* __restrict__ rd_Whh,
    const float* __restrict__ rd_bih, const float* __restrict__ rd_bhh)
{
    int bc = blockIdx.x, f = blockIdx.y, br = blockIdx.z;
    int bBase = bc * 8;
    const float* x   = br ? rd_x   : wd_x;
    const float* Wih = br ? rd_Wih : wd_Wih;
    const float* Whh = br ? rd_Whh : wd_Whh;
    const float* bih = br ? rd_bih : wd_bih;
    const float* bhh = br ? rd_bhh : wd_bhh;

    __shared__ __align__(16) float h_s[64 * 8];
    __shared__ __align__(16) float c_s[64 * 8];
    __shared__ __align__(16) float gates_s[256 * GP];
    __shared__ __align__(16) float x_s[128 * 8];

    int tid = threadIdx.x;
    for (int i = tid; i < 128 * 8; i += 256) {
        int t = i >> 3, b = i & 7;
        x_s[i] = x[(size_t)(bBase + b) * Ssz * Fdim + t * Fdim + f];
    }
    for (int i = tid; i < 64 * 8; i += 256) { h_s[i] = 0.f; c_s[i] = 0.f; }

    int g = tid;
    float wih  = Wih[f * 256 + g];
    float bias = bih[f * 256 + g] + bhh[f * 256 + g];
    u64 wih2 = pk(wih, wih), bias2 = pk(bias, bias);

    float w[64];
#pragma unroll
    for (int j = 0; j < 64; j += 4) {
        float4 v = *(const float4*)&Whh[((size_t)f * 256 + g) * 64 + j];
        w[j] = v.x; w[j + 1] = v.y; w[j + 2] = v.z; w[j + 3] = v.w;
    }
    __syncthreads();

    for (int t = 0; t < Ssz; t++) {
        u64 acc0, acc1, acc2, acc3;
        {
            const u64* xp = (const u64*)&x_s[t * 8];
            acc0 = fma2(wih2, xp[0], bias2);
            acc1 = fma2(wih2, xp[1], bias2);
            acc2 = fma2(wih2, xp[2], bias2);
            acc3 = fma2(wih2, xp[3], bias2);
        }
#pragma unroll
        for (int j = 0; j < 64; j++) {
            u64 w2 = pk(w[j], w[j]);
            const ulonglong2* hp = (const ulonglong2*)&h_s[j * 8];
            ulonglong2 hA = hp[0], hB = hp[1];
            acc0 = fma2(w2, hA.x, acc0); acc1 = fma2(w2, hA.y, acc1);
            acc2 = fma2(w2, hB.x, acc2); acc3 = fma2(w2, hB.y, acc3);
        }
        {
            u64* gp = (u64*)&gates_s[g * GP];
            gp[0] = acc0; gp[1] = acc1; gp[2] = acc2; gp[3] = acc3;
        }
        __syncthreads();
        {
            int k = tid & 63, bg = tid >> 6;
            float2 iv = *(const float2*)&gates_s[k * GP + bg * 2];
            float2 fv = *(const float2*)&gates_s[(64 + k) * GP + bg * 2];
            float2 gv = *(const float2*)&gates_s[(128 + k) * GP + bg * 2];
            float2 ov = *(const float2*)&gates_s[(192 + k) * GP + bg * 2];
            float2 cv = *(const float2*)&c_s[k * 8 + bg * 2];
            float2 cn, hn;
            cn.x = sigm_ap(fv.x) * cv.x + sigm_ap(iv.x) * tanhap(gv.x);
            hn.x = sigm_ap(ov.x) * tanhap(cn.x);
            cn.y = sigm_ap(fv.y) * cv.y + sigm_ap(iv.y) * tanhap(gv.y);
            hn.y = sigm_ap(ov.y) * tanhap(cn.y);
            *(float2*)&c_s[k * 8 + bg * 2] = cn;
            *(float2*)&h_s[k * 8 + bg * 2] = hn;
            size_t gb = ((((size_t)br * Bsz + bBase + bg * 2) * Fdim + f) * Ssz + t) * Hdim + k;
            const size_t bs = (size_t)Fdim * Ssz * Hdim;
            g_lstm[gb] = hn.x; g_lstm[gb + bs] = hn.y;
        }
        __syncthreads();
    }
}

// ---------------------------------------------------------------------------
// Proj kernel: xT in smem (34 KB), 4-row register-blocked, writes g_qk.
// ---------------------------------------------------------------------------
#define PROJ_SMEM_FLOATS (64 * XPAD)

__global__ __launch_bounds__(256, 3) void proj_kernel(
    const float* __restrict__ wd_ab, const float* __restrict__ rd_ab)
{
    int f = blockIdx.x, b = blockIdx.y, br = blockIdx.z;
    const float* ab = br ? rd_ab : wd_ab;

    extern __shared__ __align__(16) float smp[];
    float* xT = smp;   // [64][XPAD]

    int tid = threadIdx.x, lane = tid & 31, warp = tid >> 5;
    int pairW = br * Fdim + f;
    size_t pq = ((size_t)(br * Bsz + b) * Fdim + f);

    const float* xsrc = g_lstm + pq * Ssz * Hdim;
    for (int i = tid * 4; i < Ssz * Hdim; i += 1024) {
        int s = i >> 6, h = i & 63;
        float4 v = *(const float4*)&xsrc[i];
        xT[(h + 0) * XPAD + s] = v.x; xT[(h + 1) * XPAD + s] = v.y;
        xT[(h + 2) * XPAD + s] = v.z; xT[(h + 3) * XPAD + s] = v.w;
    }
    __syncthreads();

    float* qout = g_qk + pq * 16384;
#pragma unroll 1
    for (int rg = 0; rg < 4; rg++) {
        int row0 = warp * 16 + rg * 4;
        float scl = (row0 < 64) ? SCALE : 1.f;
        u64 a00, a01, a10, a11, a20, a21, a30, a31;
        {
            float b0 = ab[f * 192 + row0 + 0] * scl;
            float b1 = ab[f * 192 + row0 + 1] * scl;
            float b2 = ab[f * 192 + row0 + 2] * scl;
            float b3 = ab[f * 192 + row0 + 3] * scl;
            a00 = pk(b0, b0); a01 = a00;
            a10 = pk(b1, b1); a11 = a10;
            a20 = pk(b2, b2); a21 = a20;
            a30 = pk(b3, b3); a31 = a30;
        }
        const ulonglong2* wbase = &g_w2p[((size_t)pairW * 128 + row0) * 32];
#pragma unroll
        for (int j2 = 0; j2 < 32; j2++) {
            ulonglong2 x0 = *(const ulonglong2*)&xT[(2 * j2) * XPAD + lane * 4];
            ulonglong2 x1 = *(const ulonglong2*)&xT[(2 * j2 + 1) * XPAD + lane * 4];
            ulonglong2 w0 = __ldg(&wbase[0 * 32 + j2]);
            ulonglong2 w1 = __ldg(&wbase[1 * 32 + j2]);
            ulonglong2 w2 = __ldg(&wbase[2 * 32 + j2]);
            ulonglong2 w3 = __ldg(&wbase[3 * 32 + j2]);
            a00 = fma2(w0.x, x0.x, a00); a01 = fma2(w0.x, x0.y, a01);
            a00 = fma2(w0.y, x1.x, a00); a01 = fma2(w0.y, x1.y, a01);
            a10 = fma2(w1.x, x0.x, a10); a11 = fma2(w1.x, x0.y, a11);
            a10 = fma2(w1.y, x1.x, a10); a11 = fma2(w1.y, x1.y, a11);
            a20 = fma2(w2.x, x0.x, a20); a21 = fma2(w2.x, x0.y, a21);
            a20 = fma2(w2.y, x1.x, a20); a21 = fma2(w2.y, x1.y, a21);
            a30 = fma2(w3.x, x0.x, a30); a31 = fma2(w3.x, x0.y, a31);
            a30 = fma2(w3.y, x1.x, a30); a31 = fma2(w3.y, x1.y, a31);
        }
        *(ulonglong2*)&qout[(row0 + 0) * 128 + lane * 4] = make_ulonglong2(a00, a01);
        *(ulonglong2*)&qout[(row0 + 1) * 128 + lane * 4] = make_ulonglong2(a10, a11);
        *(ulonglong2*)&qout[(row0 + 2) * 128 + lane * 4] = make_ulonglong2(a20, a21);
        *(ulonglong2*)&qout[(row0 + 3) * 128 + lane * 4] = make_ulonglong2(a30, a31);
    }
}

// ---------------------------------------------------------------------------
// Scores kernel: kT in smem, q via __ldg broadcast. Per-head passes to keep
// regs <= 64 so __launch_bounds__(256,4) gives 8 warps/SMSP.
// ---------------------------------------------------------------------------
#define SCORES_SMEM_FLOATS (64 * XPAD + 2048 + 256 + 128 + 64)

__global__ __launch_bounds__(256, 4) void scores_kernel(
    const float* __restrict__ wd_ab, const float* __restrict__ wd_ob,
    const float* __restrict__ rd_ab, const float* __restrict__ rd_ob,
    float* __restrict__ d_out)
{
    int f = blockIdx.x, b = blockIdx.y, br = blockIdx.z;
    const float* ab = br ? rd_ab : wd_ab;
    const float* ob = br ? rd_ob : wd_ob;

    extern __shared__ __align__(16) float sms[];
    float* kT        = sms;                 // [64][XPAD]
    float* wbar_part = sms + 64 * XPAD;     // [8][2][128]
    float* wbar_s    = wbar_part + 2048;    // [2][128]
    float* xw        = wbar_s + 256;        // [2][64]
    float* o_mean    = xw + 128;            // [64]

    int tid = threadIdx.x, lane = tid & 31, warp = tid >> 5;
    int pairW = br * Fdim + f;
    size_t pq = ((size_t)(br * Bsz + b) * Fdim + f);
    const float* qk = g_qk + pq * 16384;

    // load kT (rows 64-127) coalesced into smem
    for (int i = tid * 4; i < 64 * 128; i += 1024) {
        int row = i >> 7, s = i & 127;
        float4 v = *(const float4*)&qk[(64 + row) * 128 + s];
        *(float4*)&kT[row * XPAD + s] = v;
    }
    __syncthreads();

    float wbar_reg[8] = {0, 0, 0, 0, 0, 0, 0, 0};
    float* wout_base = d_out + 128 + (size_t)br * ((size_t)Fdim * Bsz * Ssz * Ssz)
                     + (((size_t)f * Bsz + b) * Ssz) * Ssz;

#pragma unroll 1
    for (int m = 0; m < 4; m++) {
        int qi0 = (warp << 4) + (m << 2);
        float oacc[16];
        // ---- head 0 ----
        {
            u64 acc[8];
#pragma unroll
            for (int i = 0; i < 8; i++) acc[i] = 0ull;
#pragma unroll
            for (int d = 0; d < 32; d++) {
                float4 qf = __ldg((const float4*)&qk[d * 128 + qi0]);
                ulonglong2 kv = *(const ulonglong2*)&kT[d * XPAD + lane * 4];
                u64 q0 = pk(qf.x, qf.x), q1 = pk(qf.y, qf.y);
                u64 q2 = pk(qf.z, qf.z), q3 = pk(qf.w, qf.w);
                acc[0] = fma2(q0, kv.x, acc[0]); acc[1] = fma2(q0, kv.y, acc[1]);
                acc[2] = fma2(q1, kv.x, acc[2]); acc[3] = fma2(q1, kv.y, acc[3]);
                acc[4] = fma2(q2, kv.x, acc[4]); acc[5] = fma2(q2, kv.y, acc[5]);
                acc[6] = fma2(q3, kv.x, acc[6]); acc[7] = fma2(q3, kv.y, acc[7]);
            }
            float sums[4];
#pragma unroll
            for (int v = 0; v < 4; v++) {
                float2 p0 = upk(acc[2 * v]), p1 = upk(acc[2 * v + 1]);
                sums[v] = (__expf(p0.x) + __expf(p0.y)) + (__expf(p1.x) + __expf(p1.y));
            }
#pragma unroll
            for (int off = 16; off > 0; off >>= 1) {
                float t0 = __shfl_xor_sync(0xffffffffu, sums[0], off);
                float t1 = __shfl_xor_sync(0xffffffffu, sums[1], off);
                float t2 = __shfl_xor_sync(0xffffffffu, sums[2], off);
                float t3 = __shfl_xor_sync(0xffffffffu, sums[3], off);
                sums[0] += t0; sums[1] += t1; sums[2] += t2; sums[3] += t3;
            }
#pragma unroll
            for (int v = 0; v < 4; v++) {
                float inv = __fdividef(1.f, sums[v]);
                float2 p0 = upk(acc[2 * v]), p1 = upk(acc[2 * v + 1]);
                float e0 = __expf(p0.x) * inv, e1 = __expf(p0.y) * inv;
                float e2 = __expf(p1.x) * inv, e3 = __expf(p1.y) * inv;
                wbar_reg[0] += e0; wbar_reg[1] += e1;
                wbar_reg[2] += e2; wbar_reg[3] += e3;
                oacc[v * 4 + 0] = 0.5f * e0; oacc[v * 4 + 1] = 0.5f * e1;
                oacc[v * 4 + 2] = 0.5f * e2; oacc[v * 4 + 3] = 0.5f * e3;
            }
        }
        // ---- head 1 ----
        {
            u64 acc[8];
#pragma unroll
            for (int i = 0; i < 8; i++) acc[i] = 0ull;
#pragma unroll
            for (int d = 0; d < 32; d++) {
                float4 qf = __ldg((const float4*)&qk[(32 + d) * 128 + qi0]);
                ulonglong2 kv = *(const ulonglong2*)&kT[(32 + d) * XPAD + lane * 4];
                u64 q0 = pk(qf.x, qf.x), q1 = pk(qf.y, qf.y);
                u64 q2 = pk(qf.z, qf.z), q3 = pk(qf.w, qf.w);
                acc[0] = fma2(q0, kv.x, acc[0]); acc[1] = fma2(q0, kv.y, acc[1]);
                acc[2] = fma2(q1, kv.x, acc[2]); acc[3] = fma2(q1, kv.y, acc[3]);
                acc[4] = fma2(q2, kv.x, acc[4]); acc[5] = fma2(q2, kv.y, acc[5]);
                acc[6] = fma2(q3, kv.x, acc[6]); acc[7] = fma2(q3, kv.y, acc[7]);
            }
            float sums[4];
#pragma unroll
            for (int v = 0; v < 4; v++) {
                float2 p0 = upk(acc[2 * v]), p1 = upk(acc[2 * v + 1]);
                sums[v] = (__expf(p0.x) + __expf(p0.y)) + (__expf(p1.x) + __expf(p1.y));
            }
#pragma unroll
            for (int off = 16; off > 0; off >>= 1) {
                float t0 = __shfl_xor_sync(0xffffffffu, sums[0], off);
                float t1 = __shfl_xor_sync(0xffffffffu, sums[1], off);
                float t2 = __shfl_xor_sync(0xffffffffu, sums[2], off);
                float t3 = __shfl_xor_sync(0xffffffffu, sums[3], off);
                sums[0] += t0; sums[1] += t1; sums[2] += t2; sums[3] += t3;
            }
#pragma unroll
            for (int v = 0; v < 4; v++) {
                float inv = __fdividef(1.f, sums[v]);
                float2 p0 = upk(acc[2 * v]), p1 = upk(acc[2 * v + 1]);
                float e0 = __expf(p0.x) * inv, e1 = __expf(p0.y) * inv;
                float e2 = __expf(p1.x) * inv, e3 = __expf(p1.y) * inv;
                wbar_reg[4] += e0; wbar_reg[5] += e1;
                wbar_reg[6] += e2; wbar_reg[7] += e3;
                float4 o4;
                o4.x = oacc[v * 4 + 0] + 0.5f * e0;
                o4.y = oacc[v * 4 + 1] + 0.5f * e1;
                o4.z = oacc[v * 4 + 2] + 0.5f * e2;
                o4.w = oacc[v * 4 + 3] + 0.5f * e3;
                *(float4*)&wout_base[(size_t)(qi0 + v) * Ssz + lane * 4] = o4;
            }
        }
    }
    *(float4*)&wbar_part[(warp * 2 + 0) * 128 + lane * 4] =
        make_float4(wbar_reg[0], wbar_reg[1], wbar_reg[2], wbar_reg[3]);
    *(float4*)&wbar_part[(warp * 2 + 1) * 128 + lane * 4] =
        make_float4(wbar_reg[4], wbar_reg[5], wbar_reg[6], wbar_reg[7]);
    __syncthreads();

    // ---- epilogue ----
    {
        int n = tid >> 7, k = tid & 127;
        float a = 0.f;
#pragma unroll
        for (int wpi = 0; wpi < 8; wpi++) a += wbar_part[(wpi * 2 + n) * 128 + k];
        wbar_s[n * 128 + k] = a * (1.f / 128.f);
    }
    __syncthreads();
    if (tid < 128) {   // xw[n][j] = sum_k wbar_s[n][k] * x[k][j]  (x from global)
        int n = tid >> 6, j = tid & 63;
        const float* xg = g_lstm + pq * Ssz * Hdim + j;
        float a = 0.f;
#pragma unroll 4
        for (int k = 0; k < 128; k++)
            a += wbar_s[n * 128 + k] * __ldg(&xg[k * 64]);
        xw[tid] = a;
    }
    __syncthreads();
    if (tid < 64) {
        int h = tid, n = h >> 5;
        float a = ab[f * 192 + 128 + h];
        const float* wvp = g_WvT + (size_t)pairW * 4096;
        for (int j = 0; j < 64; j++) a += wvp[j * 64 + h] * xw[n * 64 + j];
        o_mean[h] = a;
    }
    __syncthreads();
    if (tid < 64) {
        int o = tid;
        float a = ob[f * 64 + o];
        const float* wop = g_WoT + (size_t)pairW * 4096;
        for (int h = 0; h < 64; h++) a += wop[h * 64 + o] * o_mean[h];
        g_pooled[(((size_t)br * Bsz + b) * Fdim + f) * 64 + o] = a;
    }
}

// ---------------------------------------------------------------------------
// Final: fused both outputs, 256 threads.
// ---------------------------------------------------------------------------
__global__ __launch_bounds__(256) void final_kernel(
    const float* __restrict__ statin, const float* __restrict__ tg,
    const float* __restrict__ d1w, const float* __restrict__ d1b,
    const float* __restrict__ d2w, const float* __restrict__ d2b,
    const float* __restrict__ t1w, const float* __restrict__ t1b,
    const float* __restrict__ t2w, const float* __restrict__ t2b,
    const float* __restrict__ fcw, const float* __restrict__ fcb,
    float* __restrict__ out)
{
    __shared__ float s1[64], sf[32], t1v[16], tf[8], r0s[8], r1s[8];
    int b = blockIdx.x, tid = threadIdx.x;
    int lane = tid & 31, warp = tid >> 5;
    if (tid < 64) {
        float a = d1b[tid];
        for (int i = 0; i < 32; i++) a += statin[b * 32 + i] * d1w[tid * 32 + i];
        s1[tid] = fmaxf(a, 0.f);
    }
    if (tid < 16) t1v[tid] = fmaxf(t1b[tid] + tg[b] * t1w[tid], 0.f);
    __syncthreads();
    if (tid < 32) {
        float a = d2b[tid];
        for (int i = 0; i < 64; i++) a += s1[i] * d2w[tid * 64 + i];
        sf[tid] = fmaxf(a, 0.f);
    }
    if (tid < 8) {
        float a = t2b[tid];
        for (int i = 0; i < 16; i++) a += t1v[i] * t2w[tid * 16 + i];
        tf[tid] = fmaxf(a, 0.f);
    }
    __syncthreads();
    float a0 = 0.f, a1 = 0.f;
    for (int i = tid; i < 2088; i += 256) {
        float cv;
        if (i < 1024)      cv = g_pooled[(size_t)b * 1024 + i];
        else if (i < 2048) cv = g_pooled[(size_t)(Bsz + b) * 1024 + (i - 1024)];
        else if (i < 2080) cv = sf[i - 2048];
        else               cv = tf[i - 2080];
        a0 = fmaf(cv, fcw[i], a0);
        a1 = fmaf(cv, fcw[2088 + i], a1);
    }
#pragma unroll
    for (int off = 16; off > 0; off >>= 1) {
        float u0 = __shfl_xor_sync(0xffffffffu, a0, off);
        float u1 = __shfl_xor_sync(0xffffffffu, a1, off);
        a0 += u0; a1 += u1;
    }
    if (lane == 0) { r0s[warp] = a0; r1s[warp] = a1; }
    __syncthreads();
    if (tid == 0) {
        float s0v = fcb[0], s1v = fcb[1];
#pragma unroll
        for (int wpi = 0; wpi < 8; wpi++) { s0v += r0s[wpi]; s1v += r1s[wpi]; }
        out[b * 2 + 0] = s0v;
        out[b * 2 + 1] = s1v;
    }
}

extern "C" void kernel_launch(void* const* d_in, const int* in_sizes, int n_in,
                              void* d_out, int out_size)
{
    const float* wd_x    = (const float*)d_in[0];
    const float* rd_x    = (const float*)d_in[1];
    const float* statin  = (const float*)d_in[2];
    const float* tg      = (const float*)d_in[3];
    const float* wd_Wih  = (const float*)d_in[4];
    const float* wd_Whh  = (const float*)d_in[5];
    const float* wd_bih  = (const float*)d_in[6];
    const float* wd_bhh  = (const float*)d_in[7];
    const float* rd_Wih  = (const float*)d_in[8];
    const float* rd_Whh  = (const float*)d_in[9];
    const float* rd_bih  = (const float*)d_in[10];
    const float* rd_bhh  = (const float*)d_in[11];
    const float* wd_aw   = (const float*)d_in[12];
    const float* wd_ab   = (const float*)d_in[13];
    const float* wd_ow   = (const float*)d_in[14];
    const float* wd_ob   = (const float*)d_in[15];
    const float* rd_aw   = (const float*)d_in[16];
    const float* rd_ab   = (const float*)d_in[17];
    const float* rd_ow   = (const float*)d_in[18];
    const float* rd_ob   = (const float*)d_in[19];
    const float* d1w     = (const float*)d_in[20];
    const float* d1b     = (const float*)d_in[21];
    const float* d2w     = (const float*)d_in[22];
    const float* d2b     = (const float*)d_in[23];
    const float* t1w     = (const float*)d_in[24];
    const float* t1b     = (const float*)d_in[25];
    const float* t2w     = (const float*)d_in[26];
    const float* t2b     = (const float*)d_in[27];
    const float* fcw     = (const float*)d_in[28];
    const float* fcb     = (const float*)d_in[29];
    float* out = (float*)d_out;

    cudaFuncSetAttribute(proj_kernel, cudaFuncAttributeMaxDynamicSharedMemorySize,
                         PROJ_SMEM_FLOATS * 4);
    cudaFuncSetAttribute(scores_kernel, cudaFuncAttributeMaxDynamicSharedMemorySize,
                         SCORES_SMEM_FLOATS * 4);

    prep_kernel<<<dim3(Fdim, 2), 256>>>(wd_aw, rd_aw, wd_ow, rd_ow);

    lstm_kernel<<<dim3(8, Fdim, 2), 256>>>(
        wd_x, rd_x, wd_Wih, wd_Whh, wd_bih, wd_bhh, rd_Wih, rd_Whh, rd_bih, rd_bhh);

    proj_kernel<<<dim3(Fdim, Bsz, 2), 256, PROJ_SMEM_FLOATS * 4>>>(wd_ab, rd_ab);

    scores_kernel<<<dim3(Fdim, Bsz, 2), 256, SCORES_SMEM_FLOATS * 4>>>(
        wd_ab, wd_ob, rd_ab, rd_ob, out);

    final_kernel<<<Bsz, 256>>>(
        statin, tg, d1w, d1b, d2w, d2b, t1w, t1b, t2w, t2b, fcw, fcb, out);
}